// round 3
// baseline (speedup 1.0000x reference)
#include <cuda_runtime.h>
#include <math.h>

#define Bv 8
#define Tv 2048
#define Dv 256
#define Ev 4
#define DEv 64
#define Hv (Bv*Ev)
#define BAND 576  // covers all |k-q| where punish*s can round to nonzero (worst-case d<510)

// Scratch (allocation-free rule: __device__ globals)
__device__ float g_Q[Hv*Tv*DEv];
__device__ float g_K[Hv*Tv*DEv];
__device__ float g_V[Hv*Tv*DEv];
__device__ float g_ctx[Hv*Tv*DEv];
__device__ float g_punish[Tv];
__device__ float g_vmean[Hv*DEv];

// ---------------------------------------------------------------------------
// punish[d] = exp(-(d*d)/theta^2), computed in double; results below the f32
// min-normal are flushed to exact 0 (FTZ reference arithmetic).
// ---------------------------------------------------------------------------
__global__ void punish_kernel(const float* __restrict__ theta) {
    int i = blockIdx.x * blockDim.x + threadIdx.x;
    if (i < Tv) {
        double fi = (double)i;
        double th = (double)theta[0];
        double p = exp(-(fi * fi) / (th * th));
        g_punish[i] = (p < 1.1754943508222875e-38) ? 0.0f : (float)p;
    }
}

// ---------------------------------------------------------------------------
// Per-head column mean of V (fully-masked softmax rows are uniform 1/T)
// ---------------------------------------------------------------------------
__global__ void vmean_kernel() {
    int h = blockIdx.x;
    int c = threadIdx.x;
    const float* vp = g_V + (size_t)h * Tv * DEv + c;
    float s0 = 0.f, s1 = 0.f, s2 = 0.f, s3 = 0.f;
    for (int k = 0; k < Tv; k += 4) {
        s0 += vp[(size_t)(k + 0) * DEv];
        s1 += vp[(size_t)(k + 1) * DEv];
        s2 += vp[(size_t)(k + 2) * DEv];
        s3 += vp[(size_t)(k + 3) * DEv];
    }
    g_vmean[h * DEv + c] = (s0 + s1 + s2 + s3) * (1.0f / 2048.0f);
}

// ---------------------------------------------------------------------------
// Projection GEMM:  Y = x @ W^T + bias,  scattered into head layout
//   Y[b,t,d] -> dst[h = b*E + d/64][q = (d%64)*32 + t/64][c = t%64]
// mask (Q,K only): zero rows with q >= seq_len[b]  (q in SCRAMBLED coords)
// ---------------------------------------------------------------------------
__global__ void proj_kernel(const float* __restrict__ x, const float* __restrict__ W,
                            const float* __restrict__ bias, const int* __restrict__ seqlen,
                            int which, int apply_mask)
{
    __shared__ float As[32][65];
    __shared__ float Ws[32][65];
    __shared__ float Cs[64][65];

    float* dst = (which == 0) ? g_Q : (which == 1) ? g_K : g_V;

    int tid = threadIdx.x;
    int token0 = blockIdx.x * 64;
    int n0 = blockIdx.y * 64;
    int tx = tid & 15, ty = tid >> 4;

    float acc[4][4];
    #pragma unroll
    for (int i = 0; i < 4; i++)
        #pragma unroll
        for (int j = 0; j < 4; j++) acc[i][j] = 0.f;

    for (int k0 = 0; k0 < Dv; k0 += 32) {
        #pragma unroll
        for (int i = 0; i < 8; i++) {
            int idx = tid + i * 256;
            int m = idx >> 5, kk = idx & 31;
            As[kk][m] = x[(size_t)(token0 + m) * Dv + k0 + kk];
            Ws[kk][m] = W[(size_t)(n0 + m) * Dv + k0 + kk];
        }
        __syncthreads();
        #pragma unroll 8
        for (int kk = 0; kk < 32; kk++) {
            float a[4], w[4];
            #pragma unroll
            for (int i = 0; i < 4; i++) a[i] = As[kk][ty * 4 + i];
            #pragma unroll
            for (int j = 0; j < 4; j++) w[j] = Ws[kk][tx * 4 + j];
            #pragma unroll
            for (int i = 0; i < 4; i++)
                #pragma unroll
                for (int j = 0; j < 4; j++)
                    acc[i][j] += a[i] * w[j];
        }
        __syncthreads();
    }

    #pragma unroll
    for (int j = 0; j < 4; j++) {
        float bj = __ldg(&bias[n0 + tx * 4 + j]);
        #pragma unroll
        for (int i = 0; i < 4; i++)
            Cs[tx * 4 + j][ty * 4 + i] = acc[i][j] + bj;
    }
    __syncthreads();

    int b = token0 / Tv;
    int t0 = token0 % Tv;
    int thi = t0 >> 6;
    int sl = seqlen[b];
    int h = b * Ev + (n0 >> 6);

    #pragma unroll
    for (int i2 = 0; i2 < 16; i2++) {
        int idx = tid + i2 * 256;
        int n = idx >> 6, m = idx & 63;
        float v = Cs[n][m];
        int q = n * 32 + thi;
        if (apply_mask && q >= sl) v = 0.0f;
        dst[((size_t)h * Tv + q) * DEv + m] = v;
    }
}

// ---------------------------------------------------------------------------
// Banded flash attention (fp32 SIMT). grid = (T/64, H), 256 threads.
// The att==0 -> -2e20 predicate is evaluated in double with the FTZ-f32
// semantics: any product below f32 min-normal flushes to 0 -> excluded.
// ---------------------------------------------------------------------------
__global__ void attn_kernel() {
    extern __shared__ float sm[];
    float* Qs = sm;                       // [64][65]
    float* Ks = Qs + 64 * 65;             // [64][65]
    float* Vs = Ks + 64 * 65;             // [64][65]
    float* Ss = Vs + 64 * 65;             // [64][65]
    float* sm_m    = Ss + 64 * 65;        // [64]
    float* sm_l    = sm_m + 64;           // [64]
    float* sm_corr = sm_l + 64;           // [64]

    int tid = threadIdx.x;
    int q0 = blockIdx.x * 64;
    int h  = blockIdx.y;
    int tx = tid & 15, ty = tid >> 4;

    const float SCALE = sqrtf(2048.0f);

    const float* Qg = g_Q + (size_t)h * Tv * DEv;
    const float* Kg = g_K + (size_t)h * Tv * DEv;
    const float* Vg = g_V + (size_t)h * Tv * DEv;

    #pragma unroll
    for (int i = 0; i < 16; i++) {
        int idx = tid + i * 256;
        int r = idx >> 6, c = idx & 63;
        Qs[r * 65 + c] = Qg[(size_t)(q0 + r) * DEv + c];
    }
    if (tid < 64) { sm_m[tid] = -2e20f; sm_l[tid] = 0.0f; }

    float acc[4][4];
    #pragma unroll
    for (int i = 0; i < 4; i++)
        #pragma unroll
        for (int j = 0; j < 4; j++) acc[i][j] = 0.f;

    __syncthreads();

    int klo = q0 - BAND; if (klo < 0) klo = 0;
    int khi = q0 + 64 + BAND; if (khi > Tv) khi = Tv;
    int kt_lo = klo >> 6, kt_hi = (khi + 63) >> 6;

    for (int kt = kt_lo; kt < kt_hi; kt++) {
        int k0 = kt * 64;
        #pragma unroll
        for (int i = 0; i < 16; i++) {
            int idx = tid + i * 256;
            int r = idx >> 6, c = idx & 63;
            Ks[r * 65 + c] = Kg[(size_t)(k0 + r) * DEv + c];
            Vs[r * 65 + c] = Vg[(size_t)(k0 + r) * DEv + c];
        }
        __syncthreads();

        // --- S = (Q K^T / sqrt(T)) * punish ; FTZ-zero -> -2e20 ---
        float s_acc[4][4];
        #pragma unroll
        for (int i = 0; i < 4; i++)
            #pragma unroll
            for (int j = 0; j < 4; j++) s_acc[i][j] = 0.f;

        #pragma unroll 8
        for (int c = 0; c < 64; c++) {
            float a[4], bb[4];
            #pragma unroll
            for (int i = 0; i < 4; i++) a[i]  = Qs[(ty * 4 + i) * 65 + c];
            #pragma unroll
            for (int j = 0; j < 4; j++) bb[j] = Ks[(tx * 4 + j) * 65 + c];
            #pragma unroll
            for (int i = 0; i < 4; i++)
                #pragma unroll
                for (int j = 0; j < 4; j++)
                    s_acc[i][j] += a[i] * bb[j];
        }
        #pragma unroll
        for (int i = 0; i < 4; i++) {
            int qg = q0 + ty * 4 + i;
            #pragma unroll
            for (int j = 0; j < 4; j++) {
                int kg = k0 + tx * 4 + j;
                int dd = kg - qg; if (dd < 0) dd = -dd;
                float p = __ldg(&g_punish[dd]);
                float s1 = s_acc[i][j] / SCALE;
                // FTZ f32-multiply zero predicate, evaluated exactly in double:
                // any |s1*p| below f32 min-normal flushes to 0 in the reference.
                double attd = (double)s1 * (double)p;
                float v;
                if (fabs(attd) < 1.1754943508222875e-38) {
                    v = -2e20f;
                } else {
                    v = (float)attd;
                }
                Ss[(ty * 4 + i) * 65 + (tx * 4 + j)] = v;
            }
        }
        __syncthreads();

        // --- row-wise online softmax transform (one thread per row) ---
        if (tid < 64) {
            int r = tid;
            float m_old = sm_m[r];
            float mt = m_old;
            #pragma unroll 8
            for (int k = 0; k < 64; k++) mt = fmaxf(mt, Ss[r * 65 + k]);
            if (mt == -2e20f) {
                sm_corr[r] = 1.0f;
                #pragma unroll 8
                for (int k = 0; k < 64; k++) Ss[r * 65 + k] = 0.0f;
            } else {
                float corr = expf(m_old - mt);   // m_old=-2e20 -> 0
                float lsum = 0.f;
                #pragma unroll 8
                for (int k = 0; k < 64; k++) {
                    float w = expf(Ss[r * 65 + k] - mt);  // -2e20 entries -> 0
                    Ss[r * 65 + k] = w;
                    lsum += w;
                }
                sm_l[r] = sm_l[r] * corr + lsum;
                sm_m[r] = mt;
                sm_corr[r] = corr;
            }
        }
        __syncthreads();

        // --- acc = acc*corr + W @ V ---
        float cr[4];
        #pragma unroll
        for (int i = 0; i < 4; i++) cr[i] = sm_corr[ty * 4 + i];
        #pragma unroll
        for (int i = 0; i < 4; i++)
            #pragma unroll
            for (int j = 0; j < 4; j++) acc[i][j] *= cr[i];

        #pragma unroll 8
        for (int k = 0; k < 64; k++) {
            float w[4], v[4];
            #pragma unroll
            for (int i = 0; i < 4; i++) w[i] = Ss[(ty * 4 + i) * 65 + k];
            #pragma unroll
            for (int j = 0; j < 4; j++) v[j] = Vs[k * 65 + (tx * 4 + j)];
            #pragma unroll
            for (int i = 0; i < 4; i++)
                #pragma unroll
                for (int j = 0; j < 4; j++)
                    acc[i][j] += w[i] * v[j];
        }
        __syncthreads();
    }

    float* ctx = g_ctx + (size_t)h * Tv * DEv;
    #pragma unroll
    for (int i = 0; i < 4; i++) {
        int r = ty * 4 + i;
        float mfin = sm_m[r];
        float l = sm_l[r];
        #pragma unroll
        for (int j = 0; j < 4; j++) {
            int c = tx * 4 + j;
            float res = (mfin == -2e20f) ? g_vmean[h * DEv + c] : (acc[i][j] / l);
            ctx[(size_t)(q0 + r) * DEv + c] = res;
        }
    }
}

// ---------------------------------------------------------------------------
// Output projection + residual:
//   ctxY[b,t,d] = g_ctx[b*E + d/64][t][d%64]   (asymmetric inverse reshape)
//   out = ctxY @ wo^T + bo + x
// ---------------------------------------------------------------------------
__global__ void outproj_kernel(const float* __restrict__ Wo, const float* __restrict__ bo,
                               const float* __restrict__ x, float* __restrict__ out)
{
    __shared__ float As[32][65];
    __shared__ float Ws[32][65];
    __shared__ float Cs[64][65];

    int tid = threadIdx.x;
    int token0 = blockIdx.x * 64;
    int n0 = blockIdx.y * 64;
    int b = token0 / Tv;
    int t0 = token0 % Tv;
    int tx = tid & 15, ty = tid >> 4;

    float acc[4][4];
    #pragma unroll
    for (int i = 0; i < 4; i++)
        #pragma unroll
        for (int j = 0; j < 4; j++) acc[i][j] = 0.f;

    for (int k0 = 0; k0 < Dv; k0 += 32) {
        #pragma unroll
        for (int i = 0; i < 8; i++) {
            int idx = tid + i * 256;
            int kk = idx & 31, m = idx >> 5;
            int k = k0 + kk;
            int t = t0 + m;
            As[kk][m] = g_ctx[(((size_t)(b * Ev + (k >> 6)) * Tv) + t) * DEv + (k & 63)];
            Ws[kk][m] = Wo[(size_t)(n0 + m) * Dv + k0 + kk];
        }
        __syncthreads();
        #pragma unroll 8
        for (int kk = 0; kk < 32; kk++) {
            float a[4], w[4];
            #pragma unroll
            for (int i = 0; i < 4; i++) a[i] = As[kk][ty * 4 + i];
            #pragma unroll
            for (int j = 0; j < 4; j++) w[j] = Ws[kk][tx * 4 + j];
            #pragma unroll
            for (int i = 0; i < 4; i++)
                #pragma unroll
                for (int j = 0; j < 4; j++)
                    acc[i][j] += a[i] * w[j];
        }
        __syncthreads();
    }

    #pragma unroll
    for (int j = 0; j < 4; j++)
        #pragma unroll
        for (int i = 0; i < 4; i++)
            Cs[tx * 4 + j][ty * 4 + i] = acc[i][j];
    __syncthreads();

    #pragma unroll
    for (int i2 = 0; i2 < 16; i2++) {
        int idx = tid + i2 * 256;
        int n = idx & 63, m = idx >> 6;
        size_t o = (size_t)(token0 + m) * Dv + n0 + n;
        out[o] = Cs[n][m] + __ldg(&bo[n0 + n]) + x[o];
    }
}

// ---------------------------------------------------------------------------
extern "C" void kernel_launch(void* const* d_in, const int* in_sizes, int n_in,
                              void* d_out, int out_size)
{
    const float* x     = (const float*)d_in[0];
    const int*   seq   = (const int*)  d_in[1];
    const float* wq    = (const float*)d_in[2];
    const float* bq    = (const float*)d_in[3];
    const float* wk    = (const float*)d_in[4];
    const float* bk    = (const float*)d_in[5];
    const float* wv    = (const float*)d_in[6];
    const float* bv    = (const float*)d_in[7];
    const float* wo    = (const float*)d_in[8];
    const float* bo    = (const float*)d_in[9];
    const float* theta = (const float*)d_in[10];
    float* out = (float*)d_out;

    punish_kernel<<<(Tv + 255) / 256, 256>>>(theta);

    dim3 pgrid(Bv * Tv / 64, Dv / 64);
    proj_kernel<<<pgrid, 256>>>(x, wq, bq, seq, 0, 1);
    proj_kernel<<<pgrid, 256>>>(x, wk, bk, seq, 1, 1);
    proj_kernel<<<pgrid, 256>>>(x, wv, bv, seq, 2, 0);

    vmean_kernel<<<Hv, DEv>>>();

    size_t shbytes = (size_t)(4 * 64 * 65 + 3 * 64) * sizeof(float);
    cudaFuncSetAttribute(attn_kernel, cudaFuncAttributeMaxDynamicSharedMemorySize,
                         (int)shbytes);
    attn_kernel<<<dim3(Tv / 64, Hv), 256, shbytes>>>();

    outproj_kernel<<<pgrid, 256>>>(wo, bo, x, out);
}

// round 4
// speedup vs baseline: 1.2406x; 1.2406x over previous
#include <cuda_runtime.h>
#include <cuda_bf16.h>
#include <math.h>

#define Bv 8
#define Tv 2048
#define Dv 256
#define Ev 4
#define DEv 64
#define Hv (Bv*Ev)
#define BAND 576  // covers all |k-q| where punish*s can round to nonzero

// Scratch (allocation-free rule: __device__ globals)
__device__ float g_Q[Hv*Tv*DEv];
__device__ float g_K[Hv*Tv*DEv];
__device__ float g_V[Hv*Tv*DEv];
__device__ float g_ctx[Hv*Tv*DEv];
__device__ float g_punish[Tv];
__device__ float g_vmean[Hv*DEv];

// ---------------------------------------------------------------------------
__global__ void punish_kernel(const float* __restrict__ theta) {
    int i = blockIdx.x * blockDim.x + threadIdx.x;
    if (i < Tv) {
        double fi = (double)i;
        double th = (double)theta[0];
        double p = exp(-(fi * fi) / (th * th));
        g_punish[i] = (p < 1.1754943508222875e-38) ? 0.0f : (float)p;
    }
}

// ---------------------------------------------------------------------------
// Per-head column mean of V (fully-masked rows -> uniform softmax = vmean)
// 256 threads: 4 partial sums per column, smem combine.
// ---------------------------------------------------------------------------
__global__ void vmean_kernel() {
    __shared__ float part[4][64];
    int h = blockIdx.x;
    int c = threadIdx.x & 63;
    int p = threadIdx.x >> 6;          // 0..3
    const float* vp = g_V + (size_t)h * Tv * DEv + c;
    float s0 = 0.f, s1 = 0.f;
    int base = p * (Tv / 4);
    for (int k = 0; k < Tv / 4; k += 2) {
        s0 += vp[(size_t)(base + k) * DEv];
        s1 += vp[(size_t)(base + k + 1) * DEv];
    }
    part[p][c] = s0 + s1;
    __syncthreads();
    if (threadIdx.x < 64) {
        // match previous pairwise-ish order closely enough (softmax-uniform path
        // tolerance is loose); sum partials
        float s = ((part[0][c] + part[1][c]) + (part[2][c] + part[3][c]));
        g_vmean[h * DEv + c] = s * (1.0f / 2048.0f);
    }
}

// ---------------------------------------------------------------------------
// Projection GEMM (unchanged from passing R3 kernel)
// ---------------------------------------------------------------------------
__global__ void proj_kernel(const float* __restrict__ x, const float* __restrict__ W,
                            const float* __restrict__ bias, const int* __restrict__ seqlen,
                            int which, int apply_mask)
{
    __shared__ float As[32][65];
    __shared__ float Ws[32][65];
    __shared__ float Cs[64][65];

    float* dst = (which == 0) ? g_Q : (which == 1) ? g_K : g_V;

    int tid = threadIdx.x;
    int token0 = blockIdx.x * 64;
    int n0 = blockIdx.y * 64;
    int tx = tid & 15, ty = tid >> 4;

    float acc[4][4];
    #pragma unroll
    for (int i = 0; i < 4; i++)
        #pragma unroll
        for (int j = 0; j < 4; j++) acc[i][j] = 0.f;

    for (int k0 = 0; k0 < Dv; k0 += 32) {
        #pragma unroll
        for (int i = 0; i < 8; i++) {
            int idx = tid + i * 256;
            int m = idx >> 5, kk = idx & 31;
            As[kk][m] = x[(size_t)(token0 + m) * Dv + k0 + kk];
            Ws[kk][m] = W[(size_t)(n0 + m) * Dv + k0 + kk];
        }
        __syncthreads();
        #pragma unroll 8
        for (int kk = 0; kk < 32; kk++) {
            float a[4], w[4];
            #pragma unroll
            for (int i = 0; i < 4; i++) a[i] = As[kk][ty * 4 + i];
            #pragma unroll
            for (int j = 0; j < 4; j++) w[j] = Ws[kk][tx * 4 + j];
            #pragma unroll
            for (int i = 0; i < 4; i++)
                #pragma unroll
                for (int j = 0; j < 4; j++)
                    acc[i][j] += a[i] * w[j];
        }
        __syncthreads();
    }

    #pragma unroll
    for (int j = 0; j < 4; j++) {
        float bj = __ldg(&bias[n0 + tx * 4 + j]);
        #pragma unroll
        for (int i = 0; i < 4; i++)
            Cs[tx * 4 + j][ty * 4 + i] = acc[i][j] + bj;
    }
    __syncthreads();

    int b = token0 / Tv;
    int t0 = token0 % Tv;
    int thi = t0 >> 6;
    int sl = seqlen[b];
    int h = b * Ev + (n0 >> 6);

    #pragma unroll
    for (int i2 = 0; i2 < 16; i2++) {
        int idx = tid + i2 * 256;
        int n = idx >> 6, m = idx & 63;
        float v = Cs[n][m];
        int q = n * 32 + thi;
        if (apply_mask && q >= sl) v = 0.0f;
        dst[((size_t)h * Tv + q) * DEv + m] = v;
    }
}

// ---------------------------------------------------------------------------
// bf16 mma.sync helpers
// ---------------------------------------------------------------------------
__device__ __forceinline__ void mma16816(float* d,
                                         unsigned a0, unsigned a1, unsigned a2, unsigned a3,
                                         unsigned b0, unsigned b1) {
    asm volatile(
        "mma.sync.aligned.m16n8k16.row.col.f32.bf16.bf16.f32 "
        "{%0,%1,%2,%3}, {%4,%5,%6,%7}, {%8,%9}, {%0,%1,%2,%3};"
        : "+f"(d[0]), "+f"(d[1]), "+f"(d[2]), "+f"(d[3])
        : "r"(a0), "r"(a1), "r"(a2), "r"(a3), "r"(b0), "r"(b1));
}

// pack two f32 -> bf16x2 reg {lo, hi}
__device__ __forceinline__ unsigned pack_bf16x2(float lo, float hi) {
    unsigned r;
    asm("cvt.rn.bf16x2.f32 %0, %1, %2;" : "=r"(r) : "f"(hi), "f"(lo));
    return r;
}

// ---------------------------------------------------------------------------
// Tensor-core banded flash attention.
// grid = (T/64, H), 256 threads (8 warps).
// Warp w: m-slice rows (w/2)*16..+16 of the 64-row q tile,
//         n-slice keys (w%2)*32..+32 of the 64-key k tile.
// smem (bf16, stride 72 to kill bank conflicts):
//   Qs[64][72], Ks[64][72], Vs[64][72]  (Vs row-major [key][d])
// ---------------------------------------------------------------------------
__global__ void __launch_bounds__(256) attn_kernel() {
    __shared__ __align__(16) unsigned char smraw[29440];
    __nv_bfloat16* Qs = (__nv_bfloat16*)(smraw);
    __nv_bfloat16* Ks = (__nv_bfloat16*)(smraw + 9216);
    __nv_bfloat16* Vs = (__nv_bfloat16*)(smraw + 18432);
    float* comb = (float*)smraw;                 // epilogue overlay (16KB over Qs/Ks)
    float* st   = (float*)(smraw + 27648);
    float* sm_m    = st;          // [64]
    float* sm_l    = st + 64;     // [64]
    float* sm_corr = st + 128;    // [64]
    float* pmax    = st + 192;    // [2][64]
    float* psum    = st + 320;    // [2][64]
    const unsigned short* Vs16 = (const unsigned short*)Vs;

    int tid = threadIdx.x;
    int wid = tid >> 5, lane = tid & 31;
    int lane4 = lane >> 2, lanem4 = lane & 3;
    int q0 = blockIdx.x * 64;
    int h  = blockIdx.y;
    int m_base = (wid >> 1) * 16;
    int ncol   = (wid & 1) * 32;
    int isupd  = ((wid & 1) == 0) && (lanem4 == 0);

    const float RSC = 1.0f / sqrtf(2048.0f);
    const double MINN = 1.1754943508222875e-38;

    const float* Qg = g_Q + (size_t)h * Tv * DEv;
    const float* Kg = g_K + (size_t)h * Tv * DEv;
    const float* Vg = g_V + (size_t)h * Tv * DEv;

    // load Q tile once (f32 -> bf16)
    #pragma unroll
    for (int i = 0; i < 16; i++) {
        int idx = tid + i * 256;
        int r = idx >> 6, c = idx & 63;
        Qs[r * 72 + c] = __float2bfloat16(Qg[(size_t)(q0 + r) * DEv + c]);
    }
    if (tid < 64) { sm_m[tid] = -2e20f; sm_l[tid] = 0.0f; }

    float o[8][4];
    #pragma unroll
    for (int u = 0; u < 8; u++)
        #pragma unroll
        for (int e = 0; e < 4; e++) o[u][e] = 0.f;

    int klo = q0 - BAND; if (klo < 0) klo = 0;
    int khi = q0 + 64 + BAND; if (khi > Tv) khi = Tv;
    int kt_lo = klo >> 6, kt_hi = (khi + 63) >> 6;

    for (int kt = kt_lo; kt < kt_hi; kt++) {
        int k0 = kt * 64;
        __syncthreads();   // protect K/V smem from previous iteration's readers
        #pragma unroll
        for (int i = 0; i < 16; i++) {
            int idx = tid + i * 256;
            int r = idx >> 6, c = idx & 63;
            Ks[r * 72 + c] = __float2bfloat16(Kg[(size_t)(k0 + r) * DEv + c]);
            Vs[r * 72 + c] = __float2bfloat16(Vg[(size_t)(k0 + r) * DEv + c]);
        }
        __syncthreads();

        // ---- S = Q @ K^T via mma (4 n-tiles per warp) ----
        float s[4][4];
        #pragma unroll
        for (int t = 0; t < 4; t++)
            #pragma unroll
            for (int e = 0; e < 4; e++) s[t][e] = 0.f;

        #pragma unroll
        for (int kk = 0; kk < 4; kk++) {
            int arow = m_base + lane4;
            int acol = kk * 16 + lanem4 * 2;
            unsigned a0 = *(const unsigned*)&Qs[arow * 72 + acol];
            unsigned a1 = *(const unsigned*)&Qs[(arow + 8) * 72 + acol];
            unsigned a2 = *(const unsigned*)&Qs[arow * 72 + acol + 8];
            unsigned a3 = *(const unsigned*)&Qs[(arow + 8) * 72 + acol + 8];
            #pragma unroll
            for (int t = 0; t < 4; t++) {
                int n = ncol + t * 8 + lane4;
                unsigned b0 = *(const unsigned*)&Ks[n * 72 + acol];
                unsigned b1 = *(const unsigned*)&Ks[n * 72 + acol + 8];
                mma16816(s[t], a0, a1, a2, a3, b0, b1);
            }
        }

        // ---- scale * punish, FTZ-zero -> -2e20 (exact double predicate) ----
        int r0g = q0 + m_base + lane4;
        int r1g = r0g + 8;
        #pragma unroll
        for (int t = 0; t < 4; t++) {
            int kb = k0 + ncol + t * 8 + lanem4 * 2;
            #pragma unroll
            for (int e = 0; e < 4; e++) {
                int kg = kb + (e & 1);
                int rg = (e < 2) ? r0g : r1g;
                int dd = kg - rg; if (dd < 0) dd = -dd;
                float p = __ldg(&g_punish[dd]);
                float s1 = s[t][e] * RSC;
                double attd = (double)s1 * (double)p;
                s[t][e] = (fabs(attd) < MINN) ? -2e20f : (float)attd;
            }
        }

        // ---- row max: local + quad shuffle, write per-warp partial ----
        float m0 = -2e20f, m1 = -2e20f;
        #pragma unroll
        for (int t = 0; t < 4; t++) {
            m0 = fmaxf(m0, fmaxf(s[t][0], s[t][1]));
            m1 = fmaxf(m1, fmaxf(s[t][2], s[t][3]));
        }
        m0 = fmaxf(m0, __shfl_xor_sync(0xffffffffu, m0, 1));
        m0 = fmaxf(m0, __shfl_xor_sync(0xffffffffu, m0, 2));
        m1 = fmaxf(m1, __shfl_xor_sync(0xffffffffu, m1, 1));
        m1 = fmaxf(m1, __shfl_xor_sync(0xffffffffu, m1, 2));
        if (lanem4 == 0) {
            pmax[(wid & 1) * 64 + m_base + lane4]     = m0;
            pmax[(wid & 1) * 64 + m_base + lane4 + 8] = m1;
        }
        __syncthreads();

        // ---- designated lanes update m / corr ----
        if (isupd) {
            #pragma unroll
            for (int rr = 0; rr < 2; rr++) {
                int r = m_base + lane4 + rr * 8;
                float mo = sm_m[r];
                float mt = fmaxf(mo, fmaxf(pmax[r], pmax[64 + r]));
                float corr = (mt == -2e20f) ? 1.0f : expf(mo - mt);
                sm_m[r] = mt;
                sm_corr[r] = corr;
            }
        }
        __syncthreads();

        // ---- exp, pack A-fragments, row-sum, rescale O ----
        float mt0 = sm_m[m_base + lane4];
        float mt1 = sm_m[m_base + lane4 + 8];
        float c0 = sm_corr[m_base + lane4];
        float c1 = sm_corr[m_base + lane4 + 8];

        float sum0 = 0.f, sum1 = 0.f;
        unsigned wa[2][4];
        #pragma unroll
        for (int t = 0; t < 4; t++) {
            float w0 = (mt0 == -2e20f) ? 0.f : expf(s[t][0] - mt0);
            float w1 = (mt0 == -2e20f) ? 0.f : expf(s[t][1] - mt0);
            float w2 = (mt1 == -2e20f) ? 0.f : expf(s[t][2] - mt1);
            float w3 = (mt1 == -2e20f) ? 0.f : expf(s[t][3] - mt1);
            sum0 += w0 + w1;
            sum1 += w2 + w3;
            wa[t >> 1][(t & 1) * 2 + 0] = pack_bf16x2(w0, w1);
            wa[t >> 1][(t & 1) * 2 + 1] = pack_bf16x2(w2, w3);
        }
        sum0 += __shfl_xor_sync(0xffffffffu, sum0, 1);
        sum0 += __shfl_xor_sync(0xffffffffu, sum0, 2);
        sum1 += __shfl_xor_sync(0xffffffffu, sum1, 1);
        sum1 += __shfl_xor_sync(0xffffffffu, sum1, 2);
        if (lanem4 == 0) {
            psum[(wid & 1) * 64 + m_base + lane4]     = sum0;
            psum[(wid & 1) * 64 + m_base + lane4 + 8] = sum1;
        }
        #pragma unroll
        for (int u = 0; u < 8; u++) {
            o[u][0] *= c0; o[u][1] *= c0;
            o[u][2] *= c1; o[u][3] *= c1;
        }
        __syncthreads();

        if (isupd) {
            #pragma unroll
            for (int rr = 0; rr < 2; rr++) {
                int r = m_base + lane4 + rr * 8;
                sm_l[r] = sm_l[r] * sm_corr[r] + psum[r] + psum[64 + r];
            }
        }

        // ---- O += W @ V (warp's 32-key slice, 2 k-steps) ----
        #pragma unroll
        for (int j = 0; j < 2; j++) {
            int kr = ncol + 16 * j + lanem4 * 2;
            #pragma unroll
            for (int u = 0; u < 8; u++) {
                int n = u * 8 + lane4;
                unsigned lo0 = Vs16[kr * 72 + n];
                unsigned hi0 = Vs16[(kr + 1) * 72 + n];
                unsigned lo1 = Vs16[(kr + 8) * 72 + n];
                unsigned hi1 = Vs16[(kr + 9) * 72 + n];
                mma16816(o[u], wa[j][0], wa[j][1], wa[j][2], wa[j][3],
                         lo0 | (hi0 << 16), lo1 | (hi1 << 16));
            }
        }
    }

    // ---- epilogue: combine warp pairs, normalize, dead-row vmean ----
    __syncthreads();
    if (wid & 1) {
        int r0 = m_base + lane4;
        #pragma unroll
        for (int u = 0; u < 8; u++) {
            int cc = u * 8 + lanem4 * 2;
            comb[r0 * 64 + cc]           = o[u][0];
            comb[r0 * 64 + cc + 1]       = o[u][1];
            comb[(r0 + 8) * 64 + cc]     = o[u][2];
            comb[(r0 + 8) * 64 + cc + 1] = o[u][3];
        }
    }
    __syncthreads();
    if (!(wid & 1)) {
        int r0 = m_base + lane4;
        int r1 = r0 + 8;
        float mf0 = sm_m[r0], mf1 = sm_m[r1];
        float l0 = sm_l[r0],  l1 = sm_l[r1];
        float* ctx = g_ctx + (size_t)h * Tv * DEv;
        #pragma unroll
        for (int u = 0; u < 8; u++) {
            int cc = u * 8 + lanem4 * 2;
            float v00 = o[u][0] + comb[r0 * 64 + cc];
            float v01 = o[u][1] + comb[r0 * 64 + cc + 1];
            float v10 = o[u][2] + comb[r1 * 64 + cc];
            float v11 = o[u][3] + comb[r1 * 64 + cc + 1];
            float out00 = (mf0 == -2e20f) ? g_vmean[h * DEv + cc]     : v00 / l0;
            float out01 = (mf0 == -2e20f) ? g_vmean[h * DEv + cc + 1] : v01 / l0;
            float out10 = (mf1 == -2e20f) ? g_vmean[h * DEv + cc]     : v10 / l1;
            float out11 = (mf1 == -2e20f) ? g_vmean[h * DEv + cc + 1] : v11 / l1;
            ctx[(size_t)(q0 + r0) * DEv + cc]     = out00;
            ctx[(size_t)(q0 + r0) * DEv + cc + 1] = out01;
            ctx[(size_t)(q0 + r1) * DEv + cc]     = out10;
            ctx[(size_t)(q0 + r1) * DEv + cc + 1] = out11;
        }
    }
}

// ---------------------------------------------------------------------------
// Output projection + residual (unchanged from passing R3 kernel)
// ---------------------------------------------------------------------------
__global__ void outproj_kernel(const float* __restrict__ Wo, const float* __restrict__ bo,
                               const float* __restrict__ x, float* __restrict__ out)
{
    __shared__ float As[32][65];
    __shared__ float Ws[32][65];
    __shared__ float Cs[64][65];

    int tid = threadIdx.x;
    int token0 = blockIdx.x * 64;
    int n0 = blockIdx.y * 64;
    int b = token0 / Tv;
    int t0 = token0 % Tv;
    int tx = tid & 15, ty = tid >> 4;

    float acc[4][4];
    #pragma unroll
    for (int i = 0; i < 4; i++)
        #pragma unroll
        for (int j = 0; j < 4; j++) acc[i][j] = 0.f;

    for (int k0 = 0; k0 < Dv; k0 += 32) {
        #pragma unroll
        for (int i = 0; i < 8; i++) {
            int idx = tid + i * 256;
            int kk = idx & 31, m = idx >> 5;
            int k = k0 + kk;
            int t = t0 + m;
            As[kk][m] = g_ctx[(((size_t)(b * Ev + (k >> 6)) * Tv) + t) * DEv + (k & 63)];
            Ws[kk][m] = Wo[(size_t)(n0 + m) * Dv + k0 + kk];
        }
        __syncthreads();
        #pragma unroll 8
        for (int kk = 0; kk < 32; kk++) {
            float a[4], w[4];
            #pragma unroll
            for (int i = 0; i < 4; i++) a[i] = As[kk][ty * 4 + i];
            #pragma unroll
            for (int j = 0; j < 4; j++) w[j] = Ws[kk][tx * 4 + j];
            #pragma unroll
            for (int i = 0; i < 4; i++)
                #pragma unroll
                for (int j = 0; j < 4; j++)
                    acc[i][j] += a[i] * w[j];
        }
        __syncthreads();
    }

    #pragma unroll
    for (int j = 0; j < 4; j++)
        #pragma unroll
        for (int i = 0; i < 4; i++)
            Cs[tx * 4 + j][ty * 4 + i] = acc[i][j];
    __syncthreads();

    #pragma unroll
    for (int i2 = 0; i2 < 16; i2++) {
        int idx = tid + i2 * 256;
        int n = idx & 63, m = idx >> 6;
        size_t oo = (size_t)(token0 + m) * Dv + n0 + n;
        out[oo] = Cs[n][m] + __ldg(&bo[n0 + n]) + x[oo];
    }
}

// ---------------------------------------------------------------------------
extern "C" void kernel_launch(void* const* d_in, const int* in_sizes, int n_in,
                              void* d_out, int out_size)
{
    const float* x     = (const float*)d_in[0];
    const int*   seq   = (const int*)  d_in[1];
    const float* wq    = (const float*)d_in[2];
    const float* bq    = (const float*)d_in[3];
    const float* wk    = (const float*)d_in[4];
    const float* bk    = (const float*)d_in[5];
    const float* wv    = (const float*)d_in[6];
    const float* bv    = (const float*)d_in[7];
    const float* wo    = (const float*)d_in[8];
    const float* bo    = (const float*)d_in[9];
    const float* theta = (const float*)d_in[10];
    float* out = (float*)d_out;

    punish_kernel<<<(Tv + 255) / 256, 256>>>(theta);

    dim3 pgrid(Bv * Tv / 64, Dv / 64);
    proj_kernel<<<pgrid, 256>>>(x, wq, bq, seq, 0, 1);
    proj_kernel<<<pgrid, 256>>>(x, wk, bk, seq, 1, 1);
    proj_kernel<<<pgrid, 256>>>(x, wv, bv, seq, 2, 0);

    vmean_kernel<<<Hv, 256>>>();

    attn_kernel<<<dim3(Tv / 64, Hv), 256>>>();

    outproj_kernel<<<pgrid, 256>>>(wo, bo, x, out);
}

// round 5
// speedup vs baseline: 3.4038x; 2.7437x over previous
#include <cuda_runtime.h>
#include <cuda_bf16.h>
#include <math.h>

#define Bv 8
#define Tv 2048
#define Dv 256
#define Ev 4
#define DEv 64
#define Hv (Bv*Ev)
#define BAND 576

// Scratch (allocation-free rule: __device__ globals)
__device__ float g_Q[Hv*Tv*DEv];
__device__ float g_K[Hv*Tv*DEv];
__device__ float g_V[Hv*Tv*DEv];
__device__ float g_ctx[Hv*Tv*DEv];
__device__ float g_punish[Tv];
__device__ float g_vmean[Hv*DEv];

// ---------------------------------------------------------------------------
__global__ void punish_kernel(const float* __restrict__ theta) {
    int i = blockIdx.x * blockDim.x + threadIdx.x;
    if (i < Tv) {
        double fi = (double)i;
        double th = (double)theta[0];
        double p = exp(-(fi * fi) / (th * th));
        g_punish[i] = (p < 1.1754943508222875e-38) ? 0.0f : (float)p;
    }
}

// ---------------------------------------------------------------------------
__global__ void vmean_kernel() {
    __shared__ float part[4][64];
    int h = blockIdx.x;
    int c = threadIdx.x & 63;
    int p = threadIdx.x >> 6;
    const float* vp = g_V + (size_t)h * Tv * DEv + c;
    float s0 = 0.f, s1 = 0.f;
    int base = p * (Tv / 4);
    for (int k = 0; k < Tv / 4; k += 2) {
        s0 += vp[(size_t)(base + k) * DEv];
        s1 += vp[(size_t)(base + k + 1) * DEv];
    }
    part[p][c] = s0 + s1;
    __syncthreads();
    if (threadIdx.x < 64) {
        float s = ((part[0][c] + part[1][c]) + (part[2][c] + part[3][c]));
        g_vmean[h * DEv + c] = s * (1.0f / 2048.0f);
    }
}

// ---------------------------------------------------------------------------
// tf32 mma helpers
// ---------------------------------------------------------------------------
__device__ __forceinline__ unsigned f2tf32(float f) {
    unsigned r;
    asm("cvt.rna.tf32.f32 %0, %1;" : "=r"(r) : "f"(f));
    return r;
}
__device__ __forceinline__ void mma_tf32(float* d,
                                         unsigned a0, unsigned a1, unsigned a2, unsigned a3,
                                         unsigned b0, unsigned b1) {
    asm volatile(
        "mma.sync.aligned.m16n8k8.row.col.f32.tf32.tf32.f32 "
        "{%0,%1,%2,%3}, {%4,%5,%6,%7}, {%8,%9}, {%0,%1,%2,%3};"
        : "+f"(d[0]), "+f"(d[1]), "+f"(d[2]), "+f"(d[3])
        : "r"(a0), "r"(a1), "r"(a2), "r"(a3), "r"(b0), "r"(b1));
}

// ---------------------------------------------------------------------------
// tf32 projection GEMM:  Y = x @ W^T + bias, scattered into head layout.
//   Y[b,t,d] -> dst[h=b*E + d/64][q=(d%64)*32 + t/64][c=t%64], mask rows q>=sl.
// Block: 128 tokens x 64 cols, 8 warps (warp = 32m x 32n), k-chunk 32.
// ---------------------------------------------------------------------------
__global__ void __launch_bounds__(256) proj_tf32_kernel(
    const float* __restrict__ x, const float* __restrict__ W,
    const float* __restrict__ bias, const int* __restrict__ seqlen,
    int which, int apply_mask)
{
    __shared__ __align__(16) unsigned char smp[35840];
    unsigned* xs = (unsigned*)smp;              // [128][36] tf32
    unsigned* ws = (unsigned*)(smp + 18432);    // [64][36]  tf32
    float* Cs = (float*)smp;                    // overlay [128][65]

    float* dst = (which == 0) ? g_Q : (which == 1) ? g_K : g_V;

    int tid = threadIdx.x;
    int wid = tid >> 5, lane = tid & 31;
    int lane4 = lane >> 2, lanem4 = lane & 3;
    int token0 = blockIdx.x * 128;
    int n0 = blockIdx.y * 64;
    int m_base = (wid & 3) * 32;
    int n_base = (wid >> 2) * 32;

    float acc[2][4][4];
    #pragma unroll
    for (int mt = 0; mt < 2; mt++)
        #pragma unroll
        for (int nt = 0; nt < 4; nt++)
            #pragma unroll
            for (int e = 0; e < 4; e++) acc[mt][nt][e] = 0.f;

    for (int k0 = 0; k0 < Dv; k0 += 32) {
        if (k0) __syncthreads();
        #pragma unroll
        for (int i = 0; i < 16; i++) {
            int idx = tid + i * 256;
            int r = idx >> 5, c = idx & 31;
            xs[r * 36 + c] = f2tf32(x[(size_t)(token0 + r) * Dv + k0 + c]);
        }
        #pragma unroll
        for (int i = 0; i < 8; i++) {
            int idx = tid + i * 256;
            int r = idx >> 5, c = idx & 31;
            ws[r * 36 + c] = f2tf32(W[(size_t)(n0 + r) * Dv + k0 + c]);
        }
        __syncthreads();

        #pragma unroll
        for (int ks = 0; ks < 4; ks++) {
            int kk = ks * 8;
            unsigned a[2][4];
            #pragma unroll
            for (int mt = 0; mt < 2; mt++) {
                int row = m_base + mt * 16 + lane4;
                a[mt][0] = xs[row * 36 + kk + lanem4];
                a[mt][1] = xs[(row + 8) * 36 + kk + lanem4];
                a[mt][2] = xs[row * 36 + kk + lanem4 + 4];
                a[mt][3] = xs[(row + 8) * 36 + kk + lanem4 + 4];
            }
            #pragma unroll
            for (int nt = 0; nt < 4; nt++) {
                int coln = n_base + nt * 8 + lane4;
                unsigned b0 = ws[coln * 36 + kk + lanem4];
                unsigned b1 = ws[coln * 36 + kk + lanem4 + 4];
                #pragma unroll
                for (int mt = 0; mt < 2; mt++)
                    mma_tf32(acc[mt][nt], a[mt][0], a[mt][1], a[mt][2], a[mt][3], b0, b1);
            }
        }
    }
    __syncthreads();

    // stage to Cs[m][n] with bias
    #pragma unroll
    for (int mt = 0; mt < 2; mt++) {
        int r0 = m_base + mt * 16 + lane4;
        #pragma unroll
        for (int nt = 0; nt < 4; nt++) {
            int cb = n_base + nt * 8 + lanem4 * 2;
            float b0 = __ldg(&bias[n0 + cb]);
            float b1 = __ldg(&bias[n0 + cb + 1]);
            Cs[r0 * 65 + cb]           = acc[mt][nt][0] + b0;
            Cs[r0 * 65 + cb + 1]       = acc[mt][nt][1] + b1;
            Cs[(r0 + 8) * 65 + cb]     = acc[mt][nt][2] + b0;
            Cs[(r0 + 8) * 65 + cb + 1] = acc[mt][nt][3] + b1;
        }
    }
    __syncthreads();

    int b = token0 / Tv;
    int t0 = token0 % Tv;
    int sl = seqlen[b];
    int h = b * Ev + blockIdx.y;

    #pragma unroll
    for (int i = 0; i < 32; i++) {
        int idx = tid + i * 256;
        int m = idx & 127, n = idx >> 7;   // m fast -> coalesced (c = t&63 runs)
        int t = t0 + m;
        int q = n * 32 + (t >> 6);
        float v = Cs[m * 65 + n];
        if (apply_mask && q >= sl) v = 0.0f;
        dst[((size_t)h * Tv + q) * DEv + (t & 63)] = v;
    }
}

// ---------------------------------------------------------------------------
// tf32 output projection + residual:
//   ctxY[b,t,k] = g_ctx[b*E + k/64][t][k%64];  out = ctxY @ wo^T + bo + x
// ---------------------------------------------------------------------------
__global__ void __launch_bounds__(256) outproj_tf32_kernel(
    const float* __restrict__ Wo, const float* __restrict__ bo,
    const float* __restrict__ x, float* __restrict__ out)
{
    __shared__ __align__(16) unsigned char smp[35840];
    unsigned* xs = (unsigned*)smp;              // [128][36]
    unsigned* ws = (unsigned*)(smp + 18432);    // [64][36]
    float* Cs = (float*)smp;                    // overlay [128][65]

    int tid = threadIdx.x;
    int wid = tid >> 5, lane = tid & 31;
    int lane4 = lane >> 2, lanem4 = lane & 3;
    int token0 = blockIdx.x * 128;
    int n0 = blockIdx.y * 64;
    int b = token0 / Tv;
    int t0 = token0 % Tv;
    int m_base = (wid & 3) * 32;
    int n_base = (wid >> 2) * 32;

    float acc[2][4][4];
    #pragma unroll
    for (int mt = 0; mt < 2; mt++)
        #pragma unroll
        for (int nt = 0; nt < 4; nt++)
            #pragma unroll
            for (int e = 0; e < 4; e++) acc[mt][nt][e] = 0.f;

    for (int k0 = 0; k0 < Dv; k0 += 32) {
        if (k0) __syncthreads();
        int hk = b * Ev + (k0 >> 6);           // k0 multiple of 32: k>>6 const per chunk
        int kc0 = k0 & 63;
        #pragma unroll
        for (int i = 0; i < 16; i++) {
            int idx = tid + i * 256;
            int r = idx >> 5, c = idx & 31;
            xs[r * 36 + c] = f2tf32(g_ctx[((size_t)hk * Tv + t0 + r) * DEv + kc0 + c]);
        }
        #pragma unroll
        for (int i = 0; i < 8; i++) {
            int idx = tid + i * 256;
            int r = idx >> 5, c = idx & 31;
            ws[r * 36 + c] = f2tf32(Wo[(size_t)(n0 + r) * Dv + k0 + c]);
        }
        __syncthreads();

        #pragma unroll
        for (int ks = 0; ks < 4; ks++) {
            int kk = ks * 8;
            unsigned a[2][4];
            #pragma unroll
            for (int mt = 0; mt < 2; mt++) {
                int row = m_base + mt * 16 + lane4;
                a[mt][0] = xs[row * 36 + kk + lanem4];
                a[mt][1] = xs[(row + 8) * 36 + kk + lanem4];
                a[mt][2] = xs[row * 36 + kk + lanem4 + 4];
                a[mt][3] = xs[(row + 8) * 36 + kk + lanem4 + 4];
            }
            #pragma unroll
            for (int nt = 0; nt < 4; nt++) {
                int coln = n_base + nt * 8 + lane4;
                unsigned b0 = ws[coln * 36 + kk + lanem4];
                unsigned b1 = ws[coln * 36 + kk + lanem4 + 4];
                #pragma unroll
                for (int mt = 0; mt < 2; mt++)
                    mma_tf32(acc[mt][nt], a[mt][0], a[mt][1], a[mt][2], a[mt][3], b0, b1);
            }
        }
    }
    __syncthreads();

    #pragma unroll
    for (int mt = 0; mt < 2; mt++) {
        int r0 = m_base + mt * 16 + lane4;
        #pragma unroll
        for (int nt = 0; nt < 4; nt++) {
            int cb = n_base + nt * 8 + lanem4 * 2;
            Cs[r0 * 65 + cb]           = acc[mt][nt][0];
            Cs[r0 * 65 + cb + 1]       = acc[mt][nt][1];
            Cs[(r0 + 8) * 65 + cb]     = acc[mt][nt][2];
            Cs[(r0 + 8) * 65 + cb + 1] = acc[mt][nt][3];
        }
    }
    __syncthreads();

    #pragma unroll
    for (int i = 0; i < 32; i++) {
        int idx = tid + i * 256;
        int n = idx & 63, m = idx >> 6;    // n fast -> coalesced global
        size_t o = (size_t)(token0 + m) * Dv + n0 + n;
        out[o] = Cs[m * 65 + n] + __ldg(&bo[n0 + n]) + x[o];
    }
}

// ---------------------------------------------------------------------------
// bf16 mma helpers (attention)
// ---------------------------------------------------------------------------
__device__ __forceinline__ void mma16816(float* d,
                                         unsigned a0, unsigned a1, unsigned a2, unsigned a3,
                                         unsigned b0, unsigned b1) {
    asm volatile(
        "mma.sync.aligned.m16n8k16.row.col.f32.bf16.bf16.f32 "
        "{%0,%1,%2,%3}, {%4,%5,%6,%7}, {%8,%9}, {%0,%1,%2,%3};"
        : "+f"(d[0]), "+f"(d[1]), "+f"(d[2]), "+f"(d[3])
        : "r"(a0), "r"(a1), "r"(a2), "r"(a3), "r"(b0), "r"(b1));
}
__device__ __forceinline__ unsigned pack_bf16x2(float lo, float hi) {
    unsigned r;
    asm("cvt.rn.bf16x2.f32 %0, %1, %2;" : "=r"(r) : "f"(hi), "f"(lo));
    return r;
}

// ---------------------------------------------------------------------------
// Tensor-core banded flash attention (fp64-free FTZ predicate).
// ---------------------------------------------------------------------------
__global__ void __launch_bounds__(256) attn_kernel() {
    __shared__ __align__(16) unsigned char smraw[29440];
    __nv_bfloat16* Qs = (__nv_bfloat16*)(smraw);
    __nv_bfloat16* Ks = (__nv_bfloat16*)(smraw + 9216);
    __nv_bfloat16* Vs = (__nv_bfloat16*)(smraw + 18432);
    float* comb = (float*)smraw;
    float* st   = (float*)(smraw + 27648);
    float* sm_m    = st;
    float* sm_l    = st + 64;
    float* sm_corr = st + 128;
    float* pmax    = st + 192;
    float* psum    = st + 320;
    const unsigned short* Vs16 = (const unsigned short*)Vs;

    int tid = threadIdx.x;
    int wid = tid >> 5, lane = tid & 31;
    int lane4 = lane >> 2, lanem4 = lane & 3;
    int q0 = blockIdx.x * 64;
    int h  = blockIdx.y;
    int m_base = (wid >> 1) * 16;
    int ncol   = (wid & 1) * 32;
    int isupd  = ((wid & 1) == 0) && (lanem4 == 0);

    const float RSC = 1.0f / sqrtf(2048.0f);

    const float* Qg = g_Q + (size_t)h * Tv * DEv;
    const float* Kg = g_K + (size_t)h * Tv * DEv;
    const float* Vg = g_V + (size_t)h * Tv * DEv;

    #pragma unroll
    for (int i = 0; i < 16; i++) {
        int idx = tid + i * 256;
        int r = idx >> 6, c = idx & 63;
        Qs[r * 72 + c] = __float2bfloat16(Qg[(size_t)(q0 + r) * DEv + c]);
    }
    if (tid < 64) { sm_m[tid] = -2e20f; sm_l[tid] = 0.0f; }

    float o[8][4];
    #pragma unroll
    for (int u = 0; u < 8; u++)
        #pragma unroll
        for (int e = 0; e < 4; e++) o[u][e] = 0.f;

    int klo = q0 - BAND; if (klo < 0) klo = 0;
    int khi = q0 + 64 + BAND; if (khi > Tv) khi = Tv;
    int kt_lo = klo >> 6, kt_hi = (khi + 63) >> 6;

    for (int kt = kt_lo; kt < kt_hi; kt++) {
        int k0 = kt * 64;
        __syncthreads();
        #pragma unroll
        for (int i = 0; i < 16; i++) {
            int idx = tid + i * 256;
            int r = idx >> 6, c = idx & 63;
            Ks[r * 72 + c] = __float2bfloat16(Kg[(size_t)(k0 + r) * DEv + c]);
            Vs[r * 72 + c] = __float2bfloat16(Vg[(size_t)(k0 + r) * DEv + c]);
        }
        __syncthreads();

        // ---- S = Q @ K^T ----
        float s[4][4];
        #pragma unroll
        for (int t = 0; t < 4; t++)
            #pragma unroll
            for (int e = 0; e < 4; e++) s[t][e] = 0.f;

        #pragma unroll
        for (int kk = 0; kk < 4; kk++) {
            int arow = m_base + lane4;
            int acol = kk * 16 + lanem4 * 2;
            unsigned a0 = *(const unsigned*)&Qs[arow * 72 + acol];
            unsigned a1 = *(const unsigned*)&Qs[(arow + 8) * 72 + acol];
            unsigned a2 = *(const unsigned*)&Qs[arow * 72 + acol + 8];
            unsigned a3 = *(const unsigned*)&Qs[(arow + 8) * 72 + acol + 8];
            #pragma unroll
            for (int t = 0; t < 4; t++) {
                int n = ncol + t * 8 + lane4;
                unsigned b0 = *(const unsigned*)&Ks[n * 72 + acol];
                unsigned b1 = *(const unsigned*)&Ks[n * 72 + acol + 8];
                mma16816(s[t], a0, a1, a2, a3, b0, b1);
            }
        }

        // ---- scale * punish; FTZ-zero -> -2e20, all in exact-scaled f32 ----
        // prod = (s1*2^64)*p == RN(s1*p)*2^64 exactly (power-of-2 scalings exact).
        // Reference FTZ flushes iff |RN(s1*p)| < 2^-126  <=>  |prod| < 2^-62.
        int r0g = q0 + m_base + lane4;
        int r1g = r0g + 8;
        #pragma unroll
        for (int t = 0; t < 4; t++) {
            int kb = k0 + ncol + t * 8 + lanem4 * 2;
            #pragma unroll
            for (int e = 0; e < 4; e++) {
                int kg = kb + (e & 1);
                int rg = (e < 2) ? r0g : r1g;
                int dd = kg - rg; if (dd < 0) dd = -dd;
                float p = __ldg(&g_punish[dd]);
                float ts = (s[t][e] * RSC) * 18446744073709551616.0f; // *2^64 exact
                float prod = ts * p;
                s[t][e] = (fabsf(prod) < 2.168404344971009e-19f)     // 2^-62
                              ? -2e20f
                              : prod * 5.421010862427522e-20f;       // *2^-64 exact
            }
        }

        // ---- row max ----
        float m0 = -2e20f, m1 = -2e20f;
        #pragma unroll
        for (int t = 0; t < 4; t++) {
            m0 = fmaxf(m0, fmaxf(s[t][0], s[t][1]));
            m1 = fmaxf(m1, fmaxf(s[t][2], s[t][3]));
        }
        m0 = fmaxf(m0, __shfl_xor_sync(0xffffffffu, m0, 1));
        m0 = fmaxf(m0, __shfl_xor_sync(0xffffffffu, m0, 2));
        m1 = fmaxf(m1, __shfl_xor_sync(0xffffffffu, m1, 1));
        m1 = fmaxf(m1, __shfl_xor_sync(0xffffffffu, m1, 2));
        if (lanem4 == 0) {
            pmax[(wid & 1) * 64 + m_base + lane4]     = m0;
            pmax[(wid & 1) * 64 + m_base + lane4 + 8] = m1;
        }
        __syncthreads();

        if (isupd) {
            #pragma unroll
            for (int rr = 0; rr < 2; rr++) {
                int r = m_base + lane4 + rr * 8;
                float mo = sm_m[r];
                float mt = fmaxf(mo, fmaxf(pmax[r], pmax[64 + r]));
                float corr = (mt == -2e20f) ? 1.0f : expf(mo - mt);
                sm_m[r] = mt;
                sm_corr[r] = corr;
            }
        }
        __syncthreads();

        float mt0 = sm_m[m_base + lane4];
        float mt1 = sm_m[m_base + lane4 + 8];
        float c0 = sm_corr[m_base + lane4];
        float c1 = sm_corr[m_base + lane4 + 8];

        float sum0 = 0.f, sum1 = 0.f;
        unsigned wa[2][4];
        #pragma unroll
        for (int t = 0; t < 4; t++) {
            float w0 = (mt0 == -2e20f) ? 0.f : expf(s[t][0] - mt0);
            float w1 = (mt0 == -2e20f) ? 0.f : expf(s[t][1] - mt0);
            float w2 = (mt1 == -2e20f) ? 0.f : expf(s[t][2] - mt1);
            float w3 = (mt1 == -2e20f) ? 0.f : expf(s[t][3] - mt1);
            sum0 += w0 + w1;
            sum1 += w2 + w3;
            wa[t >> 1][(t & 1) * 2 + 0] = pack_bf16x2(w0, w1);
            wa[t >> 1][(t & 1) * 2 + 1] = pack_bf16x2(w2, w3);
        }
        sum0 += __shfl_xor_sync(0xffffffffu, sum0, 1);
        sum0 += __shfl_xor_sync(0xffffffffu, sum0, 2);
        sum1 += __shfl_xor_sync(0xffffffffu, sum1, 1);
        sum1 += __shfl_xor_sync(0xffffffffu, sum1, 2);
        if (lanem4 == 0) {
            psum[(wid & 1) * 64 + m_base + lane4]     = sum0;
            psum[(wid & 1) * 64 + m_base + lane4 + 8] = sum1;
        }
        #pragma unroll
        for (int u = 0; u < 8; u++) {
            o[u][0] *= c0; o[u][1] *= c0;
            o[u][2] *= c1; o[u][3] *= c1;
        }
        __syncthreads();

        if (isupd) {
            #pragma unroll
            for (int rr = 0; rr < 2; rr++) {
                int r = m_base + lane4 + rr * 8;
                sm_l[r] = sm_l[r] * sm_corr[r] + psum[r] + psum[64 + r];
            }
        }

        #pragma unroll
        for (int j = 0; j < 2; j++) {
            int kr = ncol + 16 * j + lanem4 * 2;
            #pragma unroll
            for (int u = 0; u < 8; u++) {
                int n = u * 8 + lane4;
                unsigned lo0 = Vs16[kr * 72 + n];
                unsigned hi0 = Vs16[(kr + 1) * 72 + n];
                unsigned lo1 = Vs16[(kr + 8) * 72 + n];
                unsigned hi1 = Vs16[(kr + 9) * 72 + n];
                mma16816(o[u], wa[j][0], wa[j][1], wa[j][2], wa[j][3],
                         lo0 | (hi0 << 16), lo1 | (hi1 << 16));
            }
        }
    }

    __syncthreads();
    if (wid & 1) {
        int r0 = m_base + lane4;
        #pragma unroll
        for (int u = 0; u < 8; u++) {
            int cc = u * 8 + lanem4 * 2;
            comb[r0 * 64 + cc]           = o[u][0];
            comb[r0 * 64 + cc + 1]       = o[u][1];
            comb[(r0 + 8) * 64 + cc]     = o[u][2];
            comb[(r0 + 8) * 64 + cc + 1] = o[u][3];
        }
    }
    __syncthreads();
    if (!(wid & 1)) {
        int r0 = m_base + lane4;
        int r1 = r0 + 8;
        float mf0 = sm_m[r0], mf1 = sm_m[r1];
        float l0 = sm_l[r0],  l1 = sm_l[r1];
        float* ctx = g_ctx + (size_t)h * Tv * DEv;
        #pragma unroll
        for (int u = 0; u < 8; u++) {
            int cc = u * 8 + lanem4 * 2;
            float v00 = o[u][0] + comb[r0 * 64 + cc];
            float v01 = o[u][1] + comb[r0 * 64 + cc + 1];
            float v10 = o[u][2] + comb[r1 * 64 + cc];
            float v11 = o[u][3] + comb[r1 * 64 + cc + 1];
            float out00 = (mf0 == -2e20f) ? g_vmean[h * DEv + cc]     : v00 / l0;
            float out01 = (mf0 == -2e20f) ? g_vmean[h * DEv + cc + 1] : v01 / l0;
            float out10 = (mf1 == -2e20f) ? g_vmean[h * DEv + cc]     : v10 / l1;
            float out11 = (mf1 == -2e20f) ? g_vmean[h * DEv + cc + 1] : v11 / l1;
            ctx[(size_t)(q0 + r0) * DEv + cc]     = out00;
            ctx[(size_t)(q0 + r0) * DEv + cc + 1] = out01;
            ctx[(size_t)(q0 + r1) * DEv + cc]     = out10;
            ctx[(size_t)(q0 + r1) * DEv + cc + 1] = out11;
        }
    }
}

// ---------------------------------------------------------------------------
extern "C" void kernel_launch(void* const* d_in, const int* in_sizes, int n_in,
                              void* d_out, int out_size)
{
    const float* x     = (const float*)d_in[0];
    const int*   seq   = (const int*)  d_in[1];
    const float* wq    = (const float*)d_in[2];
    const float* bq    = (const float*)d_in[3];
    const float* wk    = (const float*)d_in[4];
    const float* bk    = (const float*)d_in[5];
    const float* wv    = (const float*)d_in[6];
    const float* bv    = (const float*)d_in[7];
    const float* wo    = (const float*)d_in[8];
    const float* bo    = (const float*)d_in[9];
    const float* theta = (const float*)d_in[10];
    float* out = (float*)d_out;

    punish_kernel<<<(Tv + 255) / 256, 256>>>(theta);

    dim3 pgrid(Bv * Tv / 128, Dv / 64);
    proj_tf32_kernel<<<pgrid, 256>>>(x, wq, bq, seq, 0, 1);
    proj_tf32_kernel<<<pgrid, 256>>>(x, wk, bk, seq, 1, 1);
    proj_tf32_kernel<<<pgrid, 256>>>(x, wv, bv, seq, 2, 0);

    vmean_kernel<<<Hv, 256>>>();

    attn_kernel<<<dim3(Tv / 64, Hv), 256>>>();

    outproj_tf32_kernel<<<pgrid, 256>>>(wo, bo, x, out);
}